// round 4
// baseline (speedup 1.0000x reference)
#include <cuda_runtime.h>
#include <math.h>

// Problem constants (B,C,H,W,K) = (32,8,64,64,16)
#define BATCH 32
#define CHW   (8 * 64 * 64)          // 32768 elements per batch
#define N_ELEM (BATCH * CHW)         // 1,048,576
#define KMIX  16
#define TPB   256
#define EPT   2                      // elements per thread
#define EPB   (TPB * EPT)            // 512 elements per block

__global__ void init_sldj_kernel(const float* __restrict__ sldj_in,
                                 float* __restrict__ sldj_out) {
    int i = threadIdx.x;
    if (i < BATCH) sldj_out[i] = sldj_in[i];
}

__global__ void __launch_bounds__(TPB)
coupling_kernel(const float2* __restrict__ x_change2,
                const float2* __restrict__ x_id2,
                const float2* __restrict__ a2,
                const float2* __restrict__ b2,
                const float4* __restrict__ pi4,
                const float4* __restrict__ mu4,
                const float4* __restrict__ s4,
                float2* __restrict__ out2,      // [N_ELEM/2] transformed x_change
                float2* __restrict__ out_id2,   // [N_ELEM/2] passthrough x_id
                float* __restrict__ sldj_out)   // [BATCH]
{
    const int pair = blockIdx.x * TPB + threadIdx.x;   // index into float2 arrays

    // ---- Front-batched scalar-pair loads ----
    const float2 xv  = x_change2[pair];
    const float2 av  = a2[pair];
    const float2 bv  = b2[pair];
    const float2 xid = x_id2[pair];

    // Mixture data: element e = 2*pair + e, float4 base = (2*pair+e)*4
    const int base4 = pair * 8;   // 8 consecutive float4 per tensor for the 2 elements

    // Linear-domain mixture accumulation (see R2 derivation):
    //   S1 = sum e_k*sigma_k, S0 = sum e_k*t_k*sigma_k, P = sum e_k*es_k*t_k*sigma_k^2
    float S1a = 0.f, S0a = 0.f, Pa = 0.f;
    float S1b = 0.f, S0b = 0.f, Pb = 0.f;

#pragma unroll
    for (int j = 0; j < 4; j++) {
        // element 0 chunk j lives at base4 + j; element 1 at base4 + 4 + j
        const float4 pA = pi4[base4 + j];
        const float4 pB = pi4[base4 + 4 + j];
        const float4 mA = mu4[base4 + j];
        const float4 mB = mu4[base4 + 4 + j];
        const float4 sA = s4[base4 + j];
        const float4 sB = s4[base4 + 4 + j];

        const float pa[4] = {pA.x, pA.y, pA.z, pA.w};
        const float ma[4] = {mA.x, mA.y, mA.z, mA.w};
        const float sa[4] = {sA.x, sA.y, sA.z, sA.w};
        const float pb[4] = {pB.x, pB.y, pB.z, pB.w};
        const float mb[4] = {mB.x, mB.y, mB.z, mB.w};
        const float sb[4] = {sB.x, sB.y, sB.z, sB.w};

#pragma unroll
        for (int q = 0; q < 4; q++) {
            // --- element 0 chain ---
            {
                const float ep = __expf(pa[q]);
                const float es = __expf(-sa[q]);
                const float z  = (xv.x - ma[q]) * es;
                const float t  = __expf(-z);
                const float rc = __fdividef(1.0f, 1.0f + t);
                const float r1 = ep * rc;
                const float rt = r1 * t;
                S1a += r1;
                S0a += rt;
                Pa  += rt * (es * rc);
            }
            // --- element 1 chain ---
            {
                const float ep = __expf(pb[q]);
                const float es = __expf(-sb[q]);
                const float z  = (xv.y - mb[q]) * es;
                const float t  = __expf(-z);
                const float rc = __fdividef(1.0f, 1.0f + t);
                const float r1 = ep * rc;
                const float rt = r1 * t;
                S1b += r1;
                S0b += rt;
                Pb  += rt * (es * rc);
            }
        }
    }

    // ---- epilogue per element ----
    const float lS1a = __logf(S1a), lS0a = __logf(S0a);
    const float lSea = __logf(S1a + S0a), lPa = __logf(Pa);
    const float lS1b = __logf(S1b), lS0b = __logf(S0b);
    const float lSeb = __logf(S1b + S0b), lPb = __logf(Pb);

    float2 ov;
    ov.x = (lS1a - lS0a + bv.x) * __expf(av.x);
    ov.y = (lS1b - lS0b + bv.y) * __expf(av.y);
    const float ldj = (lPa + lSea - lS1a - lS0a + av.x)
                    + (lPb + lSeb - lS1b - lS0b + av.y);

    out2[pair]    = ov;
    out_id2[pair] = xid;

    // ---- per-block reduction of ldj, then one atomic per block ----
    float v = ldj;
#pragma unroll
    for (int off = 16; off > 0; off >>= 1)
        v += __shfl_down_sync(0xFFFFFFFFu, v, off);

    __shared__ float warp_sums[TPB / 32];
    const int lane = threadIdx.x & 31;
    const int wid  = threadIdx.x >> 5;
    if (lane == 0) warp_sums[wid] = v;
    __syncthreads();
    if (wid == 0) {
        float w = (lane < TPB / 32) ? warp_sums[lane] : 0.0f;
#pragma unroll
        for (int off = 4; off > 0; off >>= 1)
            w += __shfl_down_sync(0xFFu, w, off);
        if (lane == 0) {
            const int batch = blockIdx.x / (CHW / EPB);  // 64 blocks per batch
            atomicAdd(&sldj_out[batch], w);
        }
    }
}

extern "C" void kernel_launch(void* const* d_in, const int* in_sizes, int n_in,
                              void* d_out, int out_size) {
    // Inputs (metadata order): x_change, x_id, sldj, a, b, pi, mu, s
    const float2* x_change2 = (const float2*)d_in[0];
    const float2* x_id2     = (const float2*)d_in[1];
    const float*  sldj      = (const float*)d_in[2];
    const float2* a2        = (const float2*)d_in[3];
    const float2* b2        = (const float2*)d_in[4];
    const float4* pi4       = (const float4*)d_in[5];
    const float4* mu4       = (const float4*)d_in[6];
    const float4* s4        = (const float4*)d_in[7];

    float* out      = (float*)d_out;
    float* out_id   = out + N_ELEM;
    float* sldj_out = out + 2 * N_ELEM;

    init_sldj_kernel<<<1, 32>>>(sldj, sldj_out);
    coupling_kernel<<<N_ELEM / EPB, TPB>>>(x_change2, x_id2, a2, b2,
                                           pi4, mu4, s4,
                                           (float2*)out, (float2*)out_id, sldj_out);
}

// round 5
// speedup vs baseline: 1.7028x; 1.7028x over previous
#include <cuda_runtime.h>
#include <math.h>

// Problem constants (B,C,H,W,K) = (32,8,64,64,16)
#define BATCH 32
#define CHW   (8 * 64 * 64)          // 32768 elements per batch
#define N_ELEM (BATCH * CHW)         // 1,048,576
#define KMIX  16
#define TPB   256
#define EPT   2                      // elements per thread (warp-strided pairing)
#define EPB   (TPB * EPT)            // 512 contiguous elements per block

__global__ void init_sldj_kernel(const float* __restrict__ sldj_in,
                                 float* __restrict__ sldj_out) {
    int i = threadIdx.x;
    if (i < BATCH) sldj_out[i] = sldj_in[i];
}

__global__ void __launch_bounds__(TPB)
coupling_kernel(const float*  __restrict__ x_change,
                const float*  __restrict__ x_id,
                const float*  __restrict__ a,
                const float*  __restrict__ b,
                const float4* __restrict__ pi4,
                const float4* __restrict__ mu4,
                const float4* __restrict__ s4,
                float* __restrict__ out,       // [N_ELEM]
                float* __restrict__ out_id,    // [N_ELEM]
                float* __restrict__ sldj_out)  // [BATCH]
{
    // Coalesced element pairing: e0 = base + t, e1 = base + TPB + t.
    // Both groups are lane-contiguous -> all loads fully coalesced.
    const int e0 = blockIdx.x * EPB + threadIdx.x;
    const int e1 = e0 + TPB;

    // ---- Front-batched loads for max MLP ----
    const float xA   = x_change[e0];
    const float xB   = x_change[e1];
    const float avA  = a[e0];
    const float avB  = a[e1];
    const float bvA  = b[e0];
    const float bvB  = b[e1];
    const float xidA = x_id[e0];
    const float xidB = x_id[e1];

    const int baseA = e0 * (KMIX / 4);   // float4 index, lane-stride 16B -> coalesced
    const int baseB = e1 * (KMIX / 4);

    // Linear-domain mixture accumulation (see R2 derivation):
    //   S1 = sum e_k*sigma_k, S0 = sum e_k*t_k*sigma_k, P = sum e_k*es_k*t_k*sigma_k^2
    float S1a = 0.f, S0a = 0.f, Pa = 0.f;
    float S1b = 0.f, S0b = 0.f, Pb = 0.f;

#pragma unroll
    for (int j = 0; j < 4; j++) {
        const float4 pA = pi4[baseA + j];
        const float4 mA = mu4[baseA + j];
        const float4 sA = s4[baseA + j];
        const float4 pB = pi4[baseB + j];
        const float4 mB = mu4[baseB + j];
        const float4 sB = s4[baseB + j];

        const float pa[4] = {pA.x, pA.y, pA.z, pA.w};
        const float ma[4] = {mA.x, mA.y, mA.z, mA.w};
        const float sa[4] = {sA.x, sA.y, sA.z, sA.w};
        const float pb[4] = {pB.x, pB.y, pB.z, pB.w};
        const float mb[4] = {mB.x, mB.y, mB.z, mB.w};
        const float sb[4] = {sB.x, sB.y, sB.z, sB.w};

#pragma unroll
        for (int q = 0; q < 4; q++) {
            // --- element 0 chain ---
            {
                const float ep = __expf(pa[q]);
                const float es = __expf(-sa[q]);
                const float z  = (xA - ma[q]) * es;
                const float t  = __expf(-z);
                const float rc = __fdividef(1.0f, 1.0f + t);
                const float r1 = ep * rc;
                const float rt = r1 * t;
                S1a += r1;
                S0a += rt;
                Pa  += rt * (es * rc);
            }
            // --- element 1 chain ---
            {
                const float ep = __expf(pb[q]);
                const float es = __expf(-sb[q]);
                const float z  = (xB - mb[q]) * es;
                const float t  = __expf(-z);
                const float rc = __fdividef(1.0f, 1.0f + t);
                const float r1 = ep * rc;
                const float rt = r1 * t;
                S1b += r1;
                S0b += rt;
                Pb  += rt * (es * rc);
            }
        }
    }

    // ---- epilogue per element ----
    const float lS1a = __logf(S1a), lS0a = __logf(S0a);
    const float lSea = __logf(S1a + S0a), lPa = __logf(Pa);
    const float lS1b = __logf(S1b), lS0b = __logf(S0b);
    const float lSeb = __logf(S1b + S0b), lPb = __logf(Pb);

    out[e0]    = (lS1a - lS0a + bvA) * __expf(avA);
    out[e1]    = (lS1b - lS0b + bvB) * __expf(avB);
    out_id[e0] = xidA;
    out_id[e1] = xidB;

    const float ldj = (lPa + lSea - lS1a - lS0a + avA)
                    + (lPb + lSeb - lS1b - lS0b + avB);

    // ---- per-block reduction of ldj, then one atomic per block ----
    float v = ldj;
#pragma unroll
    for (int off = 16; off > 0; off >>= 1)
        v += __shfl_down_sync(0xFFFFFFFFu, v, off);

    __shared__ float warp_sums[TPB / 32];
    const int lane = threadIdx.x & 31;
    const int wid  = threadIdx.x >> 5;
    if (lane == 0) warp_sums[wid] = v;
    __syncthreads();
    if (wid == 0) {
        float w = (lane < TPB / 32) ? warp_sums[lane] : 0.0f;
#pragma unroll
        for (int off = 4; off > 0; off >>= 1)
            w += __shfl_down_sync(0xFFu, w, off);
        if (lane == 0) {
            const int batch = blockIdx.x / (CHW / EPB);  // 64 blocks per batch
            atomicAdd(&sldj_out[batch], w);
        }
    }
}

extern "C" void kernel_launch(void* const* d_in, const int* in_sizes, int n_in,
                              void* d_out, int out_size) {
    // Inputs (metadata order): x_change, x_id, sldj, a, b, pi, mu, s
    const float* x_change = (const float*)d_in[0];
    const float* x_id     = (const float*)d_in[1];
    const float* sldj     = (const float*)d_in[2];
    const float* a        = (const float*)d_in[3];
    const float* b        = (const float*)d_in[4];
    const float4* pi4     = (const float4*)d_in[5];
    const float4* mu4     = (const float4*)d_in[6];
    const float4* s4      = (const float4*)d_in[7];

    float* out      = (float*)d_out;
    float* out_id   = out + N_ELEM;
    float* sldj_out = out + 2 * N_ELEM;

    init_sldj_kernel<<<1, 32>>>(sldj, sldj_out);
    coupling_kernel<<<N_ELEM / EPB, TPB>>>(x_change, x_id, a, b,
                                           pi4, mu4, s4,
                                           out, out_id, sldj_out);
}

// round 6
// speedup vs baseline: 2.1840x; 1.2826x over previous
#include <cuda_runtime.h>
#include <math.h>

// Problem constants (B,C,H,W,K) = (32,8,64,64,16)
#define BATCH 32
#define CHW   (8 * 64 * 64)          // 32768 elements per batch
#define N_ELEM (BATCH * CHW)         // 1,048,576
#define KMIX  16
#define TPB   128                    // smaller CTAs: higher occ, finer wave fill

__global__ void init_sldj_kernel(const float* __restrict__ sldj_in,
                                 float* __restrict__ sldj_out) {
    int i = threadIdx.x;
    if (i < BATCH) sldj_out[i] = sldj_in[i];
}

__global__ void __launch_bounds__(TPB)
coupling_kernel(const float*  __restrict__ x_change,
                const float*  __restrict__ x_id,
                const float*  __restrict__ a,
                const float*  __restrict__ b,
                const float4* __restrict__ pi4,
                const float4* __restrict__ mu4,
                const float4* __restrict__ s4,
                float* __restrict__ out,       // [N_ELEM]
                float* __restrict__ out_id,    // [N_ELEM]
                float* __restrict__ sldj_out)  // [BATCH]
{
    const int i = blockIdx.x * TPB + threadIdx.x;

    // ---- Single-use streaming loads (evict-first) ----
    const float x   = __ldcs(&x_change[i]);
    const float av  = __ldcs(&a[i]);
    const float bv  = __ldcs(&b[i]);
    const float xid = __ldcs(&x_id[i]);

    const int base4 = i * (KMIX / 4);   // float4 index, fully coalesced

    // Linear-domain mixture accumulation:
    //   e_k = exp(pi_k), es_k = exp(-s_k), z_k = (x-mu_k)*es_k
    //   t_k = exp(-z_k), sigma_k = 1/(1+t_k)
    //   S1 = sum e*sigma          (~ cdf * sum e)
    //   S0 = sum e*t*sigma        (~ (1-cdf) * sum e;  S1+S0 == sum e exactly)
    //   P  = sum e*es*t*sigma^2   (~ pdf * sum e)
    float S1 = 0.0f, S0 = 0.0f, P = 0.0f;
#pragma unroll
    for (int j = 0; j < 4; j++) {
        const float4 p4 = __ldcs(&pi4[base4 + j]);
        const float4 m4 = __ldcs(&mu4[base4 + j]);
        const float4 t4 = __ldcs(&s4[base4 + j]);

        const float pk[4] = {p4.x, p4.y, p4.z, p4.w};
        const float mk[4] = {m4.x, m4.y, m4.z, m4.w};
        const float sk[4] = {t4.x, t4.y, t4.z, t4.w};
#pragma unroll
        for (int q = 0; q < 4; q++) {
            const float ep = __expf(pk[q]);
            const float es = __expf(-sk[q]);
            const float z  = (x - mk[q]) * es;
            const float t  = __expf(-z);
            const float rc = __fdividef(1.0f, 1.0f + t);
            const float r1 = ep * rc;
            const float rt = r1 * t;
            S1 += r1;
            S0 += rt;
            P  += rt * (es * rc);
        }
    }

    const float lS1 = __logf(S1);
    const float lS0 = __logf(S0);
    const float lSe = __logf(S1 + S0);
    const float lP  = __logf(P);

    // out = (log(S1/S0) + b) * exp(a);  ldj = lP + lSe - lS1 - lS0 + a
    const float out_v    = (lS1 - lS0 + bv) * __expf(av);
    const float ldj_elem = lP + lSe - lS1 - lS0 + av;

    __stcs(&out[i], out_v);
    __stcs(&out_id[i], xid);

    // ---- per-block reduction of ldj, then one atomic per block ----
    float v = ldj_elem;
#pragma unroll
    for (int off = 16; off > 0; off >>= 1)
        v += __shfl_down_sync(0xFFFFFFFFu, v, off);

    __shared__ float warp_sums[TPB / 32];
    const int lane = threadIdx.x & 31;
    const int wid  = threadIdx.x >> 5;
    if (lane == 0) warp_sums[wid] = v;
    __syncthreads();
    if (wid == 0) {
        float w = (lane < TPB / 32) ? warp_sums[lane] : 0.0f;
#pragma unroll
        for (int off = 2; off > 0; off >>= 1)
            w += __shfl_down_sync(0xFu, w, off);
        if (lane == 0) {
            const int batch = blockIdx.x / (CHW / TPB);  // 256 blocks per batch
            atomicAdd(&sldj_out[batch], w);
        }
    }
}

extern "C" void kernel_launch(void* const* d_in, const int* in_sizes, int n_in,
                              void* d_out, int out_size) {
    // Inputs (metadata order): x_change, x_id, sldj, a, b, pi, mu, s
    const float* x_change = (const float*)d_in[0];
    const float* x_id     = (const float*)d_in[1];
    const float* sldj     = (const float*)d_in[2];
    const float* a        = (const float*)d_in[3];
    const float* b        = (const float*)d_in[4];
    const float4* pi4     = (const float4*)d_in[5];
    const float4* mu4     = (const float4*)d_in[6];
    const float4* s4      = (const float4*)d_in[7];

    float* out      = (float*)d_out;
    float* out_id   = out + N_ELEM;
    float* sldj_out = out + 2 * N_ELEM;

    init_sldj_kernel<<<1, 32>>>(sldj, sldj_out);
    coupling_kernel<<<N_ELEM / TPB, TPB>>>(x_change, x_id, a, b,
                                           pi4, mu4, s4,
                                           out, out_id, sldj_out);
}